// round 11
// baseline (speedup 1.0000x reference)
#include <cuda_runtime.h>
#include <stdint.h>

#define DD 128
#define NMAX 50000
#define EMAX 800000
#define NB ((size_t)NMAX * DD)

// scratch (static device memory — no allocs)
__device__ __align__(16) float g_buf[6 * NB];
__device__ __align__(16) float g_w[4 * DD * DD];   // tf32-rounded W, Wt, W1, W2 (natural layout)
__device__ __align__(16) float g_ww1[DD * DD];     // rnd(W_r @ W1_r)
__device__ __align__(16) float g_wi[4 * DD * DD];  // MMA-interleaved: Wt, WW1, W, W2
__device__ float g_bb1[DD];                        // b @ W1_r + b1
__device__ float g_stats[512];   // [set][{sum,sumsq}][128]
__device__ float g_bnp[512];     // [set][{mu, gamma*rstd}][128]
__device__ float g_loss;
// CSR build
__device__ int   g_cnt[NMAX + 1];
__device__ int   g_cursor[NMAX];
__device__ int   g_blksum[64];
__device__ int   g_blkoff[64];
__device__ __align__(8) int2 g_epk[EMAX];          // packed {col, val-bits}

__device__ __forceinline__ float rnd_tf32(float f) {
    uint32_t u;
    asm("cvt.rna.tf32.f32 %0, %1;" : "=r"(u) : "f"(f));
    return __uint_as_float(u);
}

__device__ __forceinline__ uint32_t rndu(uint32_t u) {
    uint32_t o;
    asm("cvt.rna.tf32.f32 %0, %1;" : "=r"(o) : "f"(__uint_as_float(u)));
    return o;
}

__device__ __forceinline__ uint32_t bnfrag(uint32_t u, float g, float bp, float alpha) {
    float v = __uint_as_float(u);
    v = fmaf(v, g, bp);
    v = fmaxf(v, 0.f) + alpha * fminf(v, 0.f);
    uint32_t o;
    asm("cvt.rna.tf32.f32 %0, %1;" : "=r"(o) : "f"(v));
    return o;
}

__device__ __forceinline__ void mma_tf32(float& d0, float& d1, float& d2, float& d3,
                                         uint32_t a0, uint32_t a1, uint32_t a2, uint32_t a3,
                                         uint32_t b0, uint32_t b1) {
    asm volatile(
        "mma.sync.aligned.m16n8k8.row.col.f32.tf32.tf32.f32 "
        "{%0,%1,%2,%3}, {%4,%5,%6,%7}, {%8,%9}, {%0,%1,%2,%3};"
        : "+f"(d0), "+f"(d1), "+f"(d2), "+f"(d3)
        : "r"(a0), "r"(a1), "r"(a2), "r"(a3), "r"(b0), "r"(b1));
}

__device__ __forceinline__ uint32_t smem_u32(const void* p) {
    uint32_t a;
    asm("{ .reg .u64 t; cvta.to.shared.u64 t, %1; cvt.u32.u64 %0, t; }" : "=r"(a) : "l"(p));
    return a;
}

__device__ __forceinline__ void cp16(uint32_t dst, const void* src, bool pred) {
    int sz = pred ? 16 : 0;
    asm volatile("cp.async.cg.shared.global [%0], [%1], 16, %2;"
                 :: "r"(dst), "l"(src), "r"(sz) : "memory");
}
#define CP_COMMIT() asm volatile("cp.async.commit_group;" ::: "memory")

// ---------------------------------------------------------------------------
// init: zero hist/stats/loss; round weight matrices into g_w
// ---------------------------------------------------------------------------
__global__ void init_kernel(const float* __restrict__ W, const float* __restrict__ Wt,
                            const float* __restrict__ W1, const float* __restrict__ W2,
                            int n) {
    int i = blockIdx.x * blockDim.x + threadIdx.x;
    if (i < 512) g_stats[i] = 0.f;
    if (i == 0) g_loss = 0.f;
    if (i <= n) g_cnt[i] = 0;
    if (i < DD * DD) {
        g_w[i]               = rnd_tf32(W[i]);
        g_w[DD * DD + i]     = rnd_tf32(Wt[i]);
        g_w[2 * DD * DD + i] = rnd_tf32(W1[i]);
        g_w[3 * DD * DD + i] = rnd_tf32(W2[i]);
    }
}

// ---------------------------------------------------------------------------
// wprod: WW1 = rnd(W_r @ W1_r); bb1 = b @ W1_r + b1
// ---------------------------------------------------------------------------
__global__ void wprod_kernel(const float* __restrict__ b, const float* __restrict__ b1) {
    int idx = blockIdx.x * 256 + threadIdx.x;     // 0..16383
    int i = idx >> 7, j = idx & 127;
    const float* W1r = g_w + 2 * DD * DD;
    float s = 0.f;
#pragma unroll 8
    for (int k = 0; k < 128; k++)
        s = fmaf(g_w[i * 128 + k], W1r[k * 128 + j], s);
    g_ww1[idx] = rnd_tf32(s);
    if (idx < 128) {
        float t = 0.f;
        for (int k = 0; k < 128; k++)
            t = fmaf(b[k], W1r[k * 128 + idx], t);
        g_bb1[idx] = t + b1[idx];
    }
}

// ---------------------------------------------------------------------------
// winterleave: pack weights into the MMA-friendly k-interleaved layout.
// g_wi[m][kb*4096 + ks*1024 + n*8 + p] = src_m[(kb*32+ks*8+kk)*128 + n]
// with p = 2*(kk&3) + (kk>>2)  (so pairs {k, k+4} are word-adjacent)
// ---------------------------------------------------------------------------
__global__ void winterleave_kernel() {
    int idx = blockIdx.x * 256 + threadIdx.x;  // 0..65535
    int m = idx >> 14;
    int r = idx & 16383;
    int kb = r >> 12, ks = (r >> 10) & 3, n = (r >> 3) & 127, p = r & 7;
    int kk = (p & 1) * 4 + (p >> 1);
    int k = kb * 32 + ks * 8 + kk;
    const float* src = (m == 0) ? g_w + DD * DD
                     : (m == 1) ? g_ww1
                     : (m == 2) ? g_w
                     : g_w + 3 * DD * DD;
    g_wi[idx] = src[k * 128 + n];
}

// ---------------------------------------------------------------------------
// CSR build: histogram -> two-level scan -> scatter (packed payload)
// ---------------------------------------------------------------------------
__global__ void hist_kernel(const int* __restrict__ erow, int E) {
    int i = blockIdx.x * blockDim.x + threadIdx.x;
    if (i < E) atomicAdd(&g_cnt[erow[i] + 1], 1);
}

__global__ __launch_bounds__(1024)
void scanA_kernel(int n) {
    __shared__ int sm[1024];
    int t = threadIdx.x;
    int i = blockIdx.x * 1024 + t;
    int v = (i <= n) ? g_cnt[i] : 0;
    sm[t] = v;
    __syncthreads();
#pragma unroll
    for (int off = 1; off < 1024; off <<= 1) {
        int u = (t >= off) ? sm[t - off] : 0;
        __syncthreads();
        sm[t] += u;
        __syncthreads();
    }
    if (i <= n) g_cnt[i] = sm[t];
    if (t == 1023) g_blksum[blockIdx.x] = sm[1023];
}

__global__ void scanB_kernel(int nb) {
    __shared__ int sm[64];
    int t = threadIdx.x;
    int v = (t < nb) ? g_blksum[t] : 0;
    sm[t] = v;
    __syncthreads();
#pragma unroll
    for (int off = 1; off < 64; off <<= 1) {
        int u = (t >= off) ? sm[t - off] : 0;
        __syncthreads();
        sm[t] += u;
        __syncthreads();
    }
    if (t < nb) g_blkoff[t] = sm[t] - v;
}

__global__ __launch_bounds__(1024)
void scanC_kernel(int n) {
    int i = blockIdx.x * 1024 + threadIdx.x;
    if (i <= n) {
        int v = g_cnt[i] + g_blkoff[blockIdx.x];
        g_cnt[i] = v;
        if (i < n) g_cursor[i] = v;
    }
}

__global__ void scatter_kernel(const int* __restrict__ erow, const int* __restrict__ ecol,
                               const float* __restrict__ eval, int E) {
    int i = blockIdx.x * blockDim.x + threadIdx.x;
    if (i >= E) return;
    int r = erow[i];
    int pos = atomicAdd(&g_cursor[r], 1);
    g_epk[pos] = make_int2(ecol[i], __float_as_int(eval[i]));
}

// ---------------------------------------------------------------------------
// CSR SpMM: one warp per row, uniform edge reads, 4-edge unroll (MLP 8).
// ---------------------------------------------------------------------------
__global__ __launch_bounds__(256)
void spmm_csr(const float* __restrict__ x, const float* __restrict__ perb,
              float* __restrict__ ax, float* __restrict__ as, int n) {
    int r = (int)((blockIdx.x * (size_t)blockDim.x + threadIdx.x) >> 5);
    if (r >= n) return;
    int lane = threadIdx.x & 31;
    int e = g_cnt[r], end = g_cnt[r + 1];
    const int off = lane * 4;
    float4 a0 = make_float4(0.f, 0.f, 0.f, 0.f);
    float4 s0 = make_float4(0.f, 0.f, 0.f, 0.f);
    float4 a1 = make_float4(0.f, 0.f, 0.f, 0.f);
    float4 s1 = make_float4(0.f, 0.f, 0.f, 0.f);
    for (; e + 4 <= end; e += 4) {
        int2 p0 = g_epk[e];
        int2 p1 = g_epk[e + 1];
        int2 p2 = g_epk[e + 2];
        int2 p3 = g_epk[e + 3];
        float v0 = __int_as_float(p0.y), v1 = __int_as_float(p1.y);
        float v2 = __int_as_float(p2.y), v3 = __int_as_float(p3.y);
        size_t c0 = (size_t)p0.x * 128 + off;
        size_t c1 = (size_t)p1.x * 128 + off;
        size_t c2 = (size_t)p2.x * 128 + off;
        size_t c3 = (size_t)p3.x * 128 + off;
        float4 x0 = *(const float4*)(x + c0);
        float4 q0 = *(const float4*)(perb + c0);
        float4 x1 = *(const float4*)(x + c1);
        float4 q1 = *(const float4*)(perb + c1);
        float4 x2 = *(const float4*)(x + c2);
        float4 q2 = *(const float4*)(perb + c2);
        float4 x3 = *(const float4*)(x + c3);
        float4 q3 = *(const float4*)(perb + c3);
        a0.x = fmaf(v0, x0.x, a0.x); a0.y = fmaf(v0, x0.y, a0.y);
        a0.z = fmaf(v0, x0.z, a0.z); a0.w = fmaf(v0, x0.w, a0.w);
        s0.x = fmaf(v0, x0.x + q0.x, s0.x); s0.y = fmaf(v0, x0.y + q0.y, s0.y);
        s0.z = fmaf(v0, x0.z + q0.z, s0.z); s0.w = fmaf(v0, x0.w + q0.w, s0.w);
        a1.x = fmaf(v1, x1.x, a1.x); a1.y = fmaf(v1, x1.y, a1.y);
        a1.z = fmaf(v1, x1.z, a1.z); a1.w = fmaf(v1, x1.w, a1.w);
        s1.x = fmaf(v1, x1.x + q1.x, s1.x); s1.y = fmaf(v1, x1.y + q1.y, s1.y);
        s1.z = fmaf(v1, x1.z + q1.z, s1.z); s1.w = fmaf(v1, x1.w + q1.w, s1.w);
        a0.x = fmaf(v2, x2.x, a0.x); a0.y = fmaf(v2, x2.y, a0.y);
        a0.z = fmaf(v2, x2.z, a0.z); a0.w = fmaf(v2, x2.w, a0.w);
        s0.x = fmaf(v2, x2.x + q2.x, s0.x); s0.y = fmaf(v2, x2.y + q2.y, s0.y);
        s0.z = fmaf(v2, x2.z + q2.z, s0.z); s0.w = fmaf(v2, x2.w + q2.w, s0.w);
        a1.x = fmaf(v3, x3.x, a1.x); a1.y = fmaf(v3, x3.y, a1.y);
        a1.z = fmaf(v3, x3.z, a1.z); a1.w = fmaf(v3, x3.w, a1.w);
        s1.x = fmaf(v3, x3.x + q3.x, s1.x); s1.y = fmaf(v3, x3.y + q3.y, s1.y);
        s1.z = fmaf(v3, x3.z + q3.z, s1.z); s1.w = fmaf(v3, x3.w + q3.w, s1.w);
    }
    for (; e < end; e++) {
        int2 p0 = g_epk[e];
        float v0 = __int_as_float(p0.y);
        size_t c0 = (size_t)p0.x * 128 + off;
        float4 x0 = *(const float4*)(x + c0);
        float4 q0 = *(const float4*)(perb + c0);
        a0.x = fmaf(v0, x0.x, a0.x); a0.y = fmaf(v0, x0.y, a0.y);
        a0.z = fmaf(v0, x0.z, a0.z); a0.w = fmaf(v0, x0.w, a0.w);
        s0.x = fmaf(v0, x0.x + q0.x, s0.x); s0.y = fmaf(v0, x0.y + q0.y, s0.y);
        s0.z = fmaf(v0, x0.z + q0.z, s0.z); s0.w = fmaf(v0, x0.w + q0.w, s0.w);
    }
    a0.x += a1.x; a0.y += a1.y; a0.z += a1.z; a0.w += a1.w;
    s0.x += s1.x; s0.y += s1.y; s0.z += s1.z; s0.w += s1.w;
    size_t ro = (size_t)r * 128 + off;
    *(float4*)(ax + ro) = a0;
    *(float4*)(as + ro) = s0;
}

// ---------------------------------------------------------------------------
// Pipelined tf32 GEMM: 3-stage cp.async, BK=32 x 4 chunks, 512 thr / 16 warps,
// interleaved-B LDS.64 fragments (12 LDS + 8 MMA per k-step per warp).
// PHASE 0 (5 sets): 0: TY=AX@Wt+bt       1: U1=AX@WW1+bb1 (stats0)
//                   2: TX=AS@Wt+bt       3: emb=AS@W+b+x+perb
//                   4: U2=AS@WW1+bb1 (stats1)
// PHASE 2 (2 sets): p=PReLU(BN(U))@W2+b2 (no store), fused BYOL loss vs T
// ---------------------------------------------------------------------------
#define AP_ 36
#define ACH (128 * AP_)      // A chunk words
#define BCH 4096             // B chunk words (interleaved, no padding)
#define RED_OFF (3 * ACH + 3 * BCH)
#define SMEM_BYTES ((RED_OFF + 384 + 256) * 4)

template <int PHASE>
__global__ __launch_bounds__(512, 2)
void fgemm(const float* __restrict__ AX, const float* __restrict__ AS,
           float* __restrict__ TY, float* __restrict__ TX,
           float* __restrict__ U1, float* __restrict__ U2,
           const float* __restrict__ b, const float* __restrict__ bt,
           const float* __restrict__ b2,
           const float* __restrict__ beta, const float* __restrict__ alphap,
           const float* __restrict__ xsrc, const float* __restrict__ psrc,
           float* __restrict__ emb, int n) {
    extern __shared__ float smf[];
    uint32_t sb = smem_u32(smf);
    float* redf = smf + RED_OFF;
    float* sG   = smf + RED_OFF + 384;
    float* sBp  = sG + 128;

    const int tid = threadIdx.x;
    const int wid = tid >> 5;
    const int lane = tid & 31;
    const int grp = lane >> 2;
    const int tig = lane & 3;
    const int wm = wid >> 1;
    const int wn = wid & 1;
    const int set = blockIdx.x;
    const int m0 = blockIdx.y * 128;

    const float* A;
    const float* Bm;
    const float* bias;
    float* outp = nullptr;
    const float* Tm = nullptr;
    bool do_emb = false, do_stats = false;
    int statset = 0;
    if (PHASE == 0) {
        A = (set >= 2) ? AS : AX;
        if (set == 0)      { Bm = g_wi;                bias = bt;    outp = TY; }
        else if (set == 1) { Bm = g_wi + 1 * DD * DD;  bias = g_bb1; outp = U1; do_stats = true; statset = 0; }
        else if (set == 2) { Bm = g_wi;                bias = bt;    outp = TX; }
        else if (set == 3) { Bm = g_wi + 2 * DD * DD;  bias = b;     outp = emb; do_emb = true; }
        else               { Bm = g_wi + 1 * DD * DD;  bias = g_bb1; outp = U2; do_stats = true; statset = 1; }
    } else {
        A = set ? U2 : U1;
        Bm = g_wi + 3 * DD * DD;
        bias = b2;
        Tm = set ? TY : TX;
    }

    if (tid < 384) redf[tid] = 0.f;
    float alpha = 0.f;
    if (PHASE == 2) {
        alpha = __ldg(alphap);
        if (tid < 128) {
            float mu = g_bnp[set * 256 + tid];
            float g  = g_bnp[set * 256 + 128 + tid];
            sG[tid] = g;
            sBp[tid] = beta[tid] - mu * g;
        }
    }

    float acc[8][4];
#pragma unroll
    for (int j = 0; j < 8; j++)
#pragma unroll
        for (int q = 0; q < 4; q++) acc[j][q] = 0.f;

    auto issue = [&](int c, int s) {
        const int kb = c * 32;
#pragma unroll
        for (int j = 0; j < 2; j++) {
            int f = tid + j * 512;
            int row = f >> 3, c4 = f & 7;
            uint32_t dst = sb + (uint32_t)((s * ACH + row * AP_ + c4 * 4) * 4);
            cp16(dst, A + (size_t)(m0 + row) * 128 + kb + c4 * 4, (m0 + row) < n);
        }
#pragma unroll
        for (int j = 0; j < 2; j++) {
            int f = tid + j * 512;           // 0..1023 sixteen-byte chunks
            uint32_t dst = sb + (uint32_t)((3 * ACH + s * BCH + f * 4) * 4);
            cp16(dst, Bm + c * 4096 + f * 4, true);
        }
        CP_COMMIT();
    };

    auto compute = [&](int st, int c) {
        const uint32_t* Ab = (const uint32_t*)(smf + st * ACH);
        const uint32_t* Bb = (const uint32_t*)(smf + 3 * ACH + st * BCH);
#pragma unroll
        for (int ks = 0; ks < 4; ks++) {
            const int k0 = ks * 8;
            const uint32_t* a0p = Ab + (wm * 16 + grp) * AP_ + k0 + tig;
            const uint32_t* a1p = a0p + 8 * AP_;
            uint32_t af0 = a0p[0], af1 = a1p[0], af2 = a0p[4], af3 = a1p[4];
            if (PHASE == 2) {
                int kA = c * 32 + k0 + tig;
                float gA = sG[kA], bA = sBp[kA];
                float gB = sG[kA + 4], bB = sBp[kA + 4];
                af0 = bnfrag(af0, gA, bA, alpha);
                af1 = bnfrag(af1, gA, bA, alpha);
                af2 = bnfrag(af2, gB, bB, alpha);
                af3 = bnfrag(af3, gB, bB, alpha);
            } else {
                af0 = rndu(af0); af1 = rndu(af1);
                af2 = rndu(af2); af3 = rndu(af3);
            }
            const uint32_t* bbase = Bb + ks * 1024 + (wn * 64 + grp) * 8 + tig * 2;
#pragma unroll
            for (int ni = 0; ni < 8; ni++) {
                uint2 bv = *(const uint2*)(bbase + ni * 64);
                mma_tf32(acc[ni][0], acc[ni][1], acc[ni][2], acc[ni][3],
                         af0, af1, af2, af3, bv.x, bv.y);
            }
        }
    };

    issue(0, 0);
    issue(1, 1);
    issue(2, 2);
    asm volatile("cp.async.wait_group 2;" ::: "memory");
    __syncthreads();
    compute(0, 0);
    __syncthreads();
    issue(3, 0);
    asm volatile("cp.async.wait_group 2;" ::: "memory");
    __syncthreads();
    compute(1, 1);
    __syncthreads();
    asm volatile("cp.async.wait_group 1;" ::: "memory");
    __syncthreads();
    compute(2, 2);
    __syncthreads();
    asm volatile("cp.async.wait_group 0;" ::: "memory");
    __syncthreads();
    compute(0, 3);   // stage 0 holds chunk 3

    const int r0 = m0 + wm * 16 + grp;
    const int r1 = r0 + 8;
    const bool ok0 = r0 < n, ok1 = r1 < n;

    if (PHASE == 2) {
        float pp0 = 0.f, tt0 = 0.f, pt0 = 0.f;
        float pp1 = 0.f, tt1 = 0.f, pt1 = 0.f;
#pragma unroll
        for (int ni = 0; ni < 8; ni++) {
            int col = wn * 64 + ni * 8 + tig * 2;
            float2 bv = *(const float2*)(bias + col);
            float c0 = acc[ni][0] + bv.x, c1 = acc[ni][1] + bv.y;
            float c2 = acc[ni][2] + bv.x, c3 = acc[ni][3] + bv.y;
            if (ok0) {
                float2 t = *(const float2*)(Tm + (size_t)r0 * 128 + col);
                pp0 += c0 * c0 + c1 * c1;
                tt0 += t.x * t.x + t.y * t.y;
                pt0 += c0 * t.x + c1 * t.y;
            }
            if (ok1) {
                float2 t = *(const float2*)(Tm + (size_t)r1 * 128 + col);
                pp1 += c2 * c2 + c3 * c3;
                tt1 += t.x * t.x + t.y * t.y;
                pt1 += c2 * t.x + c3 * t.y;
            }
        }
#pragma unroll
        for (int msk = 1; msk <= 2; msk <<= 1) {
            pp0 += __shfl_xor_sync(0xffffffffu, pp0, msk);
            tt0 += __shfl_xor_sync(0xffffffffu, tt0, msk);
            pt0 += __shfl_xor_sync(0xffffffffu, pt0, msk);
            pp1 += __shfl_xor_sync(0xffffffffu, pp1, msk);
            tt1 += __shfl_xor_sync(0xffffffffu, tt1, msk);
            pt1 += __shfl_xor_sync(0xffffffffu, pt1, msk);
        }
        if (tig == 0) {
            int lr0 = wm * 16 + grp, lr1 = lr0 + 8;
            atomicAdd(&redf[lr0], pp0);
            atomicAdd(&redf[128 + lr0], tt0);
            atomicAdd(&redf[256 + lr0], pt0);
            atomicAdd(&redf[lr1], pp1);
            atomicAdd(&redf[128 + lr1], tt1);
            atomicAdd(&redf[256 + lr1], pt1);
        }
        __syncthreads();
        if (tid < 128) {
            float l = 0.f;
            if (m0 + tid < n)
                l = 2.f - 2.f * redf[256 + tid] * rsqrtf(redf[tid]) * rsqrtf(redf[128 + tid]);
#pragma unroll
            for (int o = 16; o; o >>= 1) l += __shfl_xor_sync(0xffffffffu, l, o);
            if (lane == 0) redf[320 + wid] = l;
        }
        __syncthreads();
        if (tid == 0)
            atomicAdd(&g_loss, redf[320] + redf[321] + redf[322] + redf[323]);
        return;
    }

    // PHASE 0 store epilogue
#pragma unroll
    for (int ni = 0; ni < 8; ni++) {
        int col = wn * 64 + ni * 8 + tig * 2;
        float2 bv = *(const float2*)(bias + col);
        float c0 = acc[ni][0] + bv.x, c1 = acc[ni][1] + bv.y;
        float c2 = acc[ni][2] + bv.x, c3 = acc[ni][3] + bv.y;
        if (ok0) {
            size_t o0 = (size_t)r0 * 128 + col;
            if (do_emb) {
                float2 xv = *(const float2*)(xsrc + o0);
                float2 pv = *(const float2*)(psrc + o0);
                *(float2*)(outp + o0) = make_float2(c0 + xv.x + pv.x, c1 + xv.y + pv.y);
            } else {
                *(float2*)(outp + o0) = make_float2(c0, c1);
            }
        }
        if (ok1) {
            size_t o1 = (size_t)r1 * 128 + col;
            if (do_emb) {
                float2 xv = *(const float2*)(xsrc + o1);
                float2 pv = *(const float2*)(psrc + o1);
                *(float2*)(outp + o1) = make_float2(c2 + xv.x + pv.x, c3 + xv.y + pv.y);
            } else {
                *(float2*)(outp + o1) = make_float2(c2, c3);
            }
        }
        if (do_stats) {
            float s0 = (ok0 ? c0 : 0.f) + (ok1 ? c2 : 0.f);
            float s1 = (ok0 ? c1 : 0.f) + (ok1 ? c3 : 0.f);
            float q0 = (ok0 ? c0 * c0 : 0.f) + (ok1 ? c2 * c2 : 0.f);
            float q1 = (ok0 ? c1 * c1 : 0.f) + (ok1 ? c3 * c3 : 0.f);
#pragma unroll
            for (int msk = 4; msk <= 16; msk <<= 1) {
                s0 += __shfl_xor_sync(0xffffffffu, s0, msk);
                s1 += __shfl_xor_sync(0xffffffffu, s1, msk);
                q0 += __shfl_xor_sync(0xffffffffu, q0, msk);
                q1 += __shfl_xor_sync(0xffffffffu, q1, msk);
            }
            if (grp == 0) {
                atomicAdd(&redf[col], s0);
                atomicAdd(&redf[col + 1], s1);
                atomicAdd(&redf[128 + col], q0);
                atomicAdd(&redf[128 + col + 1], q1);
            }
        }
    }

    if (do_stats) {
        __syncthreads();
        if (tid < 256)
            atomicAdd(&g_stats[statset * 256 + tid], redf[tid]);
    }
}

// ---------------------------------------------------------------------------
__global__ void bn_finalize(const float* __restrict__ gamma, int n) {
    int t = threadIdx.x;
    int set = t >> 7, c = t & 127;
    float s = g_stats[set * 256 + c];
    float q = g_stats[set * 256 + 128 + c];
    float mu = s / (float)n;
    float var = q / (float)n - mu * mu;
    float g = gamma[c] * rsqrtf(var + 1e-5f);
    g_bnp[set * 256 + c] = mu;
    g_bnp[set * 256 + 128 + c] = g;
}

__global__ void finish_kernel(float* __restrict__ out, int n, size_t idx) {
    out[idx] = g_loss / (float)n;
}

// ---------------------------------------------------------------------------
extern "C" void kernel_launch(void* const* d_in, const int* in_sizes, int n_in,
                              void* d_out, int out_size) {
    const float* x     = (const float*)d_in[0];
    const float* perb  = (const float*)d_in[1];
    const int*   erow  = (const int*)d_in[2];
    const int*   ecol  = (const int*)d_in[3];
    const float* eval  = (const float*)d_in[4];
    const float* W     = (const float*)d_in[5];
    const float* b     = (const float*)d_in[6];
    const float* Wt    = (const float*)d_in[7];
    const float* bt    = (const float*)d_in[8];
    const float* W1    = (const float*)d_in[9];
    const float* b1    = (const float*)d_in[10];
    const float* gamma = (const float*)d_in[11];
    const float* beta  = (const float*)d_in[12];
    const float* alpha = (const float*)d_in[13];
    const float* W2    = (const float*)d_in[14];
    const float* b2    = (const float*)d_in[15];

    const int n = in_sizes[0] / DD;
    const int E = in_sizes[2];
    float* out = (float*)d_out;

    float* buf = nullptr;
    cudaGetSymbolAddress((void**)&buf, g_buf);

    float* AX  = buf + 0 * NB;   // adj@x
    float* AS  = buf + 1 * NB;   // adj@(x+perb)
    float* TY  = buf + 2 * NB;   // target_y
    float* TX  = buf + 3 * NB;   // target_x
    float* U1  = buf + 4 * NB;
    float* U2  = buf + 5 * NB;

    cudaFuncSetAttribute(fgemm<0>, cudaFuncAttributeMaxDynamicSharedMemorySize, SMEM_BYTES);
    cudaFuncSetAttribute(fgemm<2>, cudaFuncAttributeMaxDynamicSharedMemorySize, SMEM_BYTES);

    // init + composed/interleaved weights + CSR build
    init_kernel<<<(n + 1 + 255) / 256, 256>>>(W, Wt, W1, W2, n);
    wprod_kernel<<<64, 256>>>(b, b1);
    winterleave_kernel<<<256, 256>>>();
    hist_kernel<<<(E + 255) / 256, 256>>>(erow, E);
    const int nblk = (n + 1 + 1023) / 1024;
    scanA_kernel<<<nblk, 1024>>>(n);
    scanB_kernel<<<1, 64>>>(nblk);
    scanC_kernel<<<nblk, 1024>>>(n);
    scatter_kernel<<<(E + 255) / 256, 256>>>(erow, ecol, eval, E);

    // gather-only SpMM (no atomics)
    spmm_csr<<<(int)(((long long)n * 32 + 255) / 256), 256>>>(x, perb, AX, AS, n);

    const int gbx = (n + 127) / 128;
    dim3 g5(5, gbx, 1), g2(2, gbx, 1);

    // merged encoder + predictor L1: TY, U1(stats), TX, emb, U2(stats)
    fgemm<0><<<g5, 512, SMEM_BYTES>>>(AX, AS, TY, TX, U1, U2,
                                      b, bt, b2, beta, alpha, x, perb, out, n);
    bn_finalize<<<1, 256>>>(gamma, n);
    // predictor L2 (fused BN+PReLU) + fused BYOL loss
    fgemm<2><<<g2, 512, SMEM_BYTES>>>(AX, AS, TY, TX, U1, U2,
                                      b, bt, b2, beta, alpha, x, perb, out, n);

    finish_kernel<<<1, 1>>>(out, n, (size_t)n * DD);
}